// round 10
// baseline (speedup 1.0000x reference)
#include <cuda_runtime.h>
#include <cstdint>
#include <math_constants.h>

#define KTOP    30
#define COLS    1024
#define WPB     8            // warps per block
#define TPB     (WPB * 32)
#define CAP     64           // candidate slots per warp (2 regs/lane in sort)

// dynamic smem layout (bytes)
#define OFF_BUFA  0
#define OFF_BUFB  (WPB * COLS * 4)
#define OFF_SLOT  (2 * WPB * COLS * 4)
#define OFF_BM    (OFF_SLOT + WPB * CAP * 8)
#define SMEM_SZ   (OFF_BM + WPB * 32 * 4)

// deterministic global accumulators (integer atomics commute exactly)
__device__ unsigned long long g_cnt;     // sum of per-row intersection counts
__device__ unsigned long long g_diffx;   // sum of per-block diff, fixed-point 2^30
__device__ unsigned g_arrive;

// ---------- cp.async helpers ----------
__device__ __forceinline__ unsigned smem_u32(const void* p) {
    return (unsigned)__cvta_generic_to_shared(p);
}
__device__ __forceinline__ void cp_async16(unsigned saddr, const void* gptr) {
    asm volatile("cp.async.cg.shared.global [%0], [%1], 16;\n"
                 :: "r"(saddr), "l"(gptr) : "memory");
}
__device__ __forceinline__ void cp_commit() {
    asm volatile("cp.async.commit_group;\n" ::: "memory");
}
__device__ __forceinline__ void cp_wait1() {   // wait until <=1 group pending
    asm volatile("cp.async.wait_group 1;\n" ::: "memory");
}

// ---------- monotone float<->uint key (only used in the cold fallback) ----------
__device__ __forceinline__ unsigned fmono(float f) {
    unsigned u = __float_as_uint(f);
    return u ^ (0x80000000u | (unsigned)((int)u >> 31));
}
__device__ __forceinline__ float fdemono(unsigned k) {
    unsigned u = k ^ (0x80000000u | ~(unsigned)((int)k >> 31));
    return __uint_as_float(u);
}

// ---------- cross-lane bitonic: 2 regs/lane (64 values) -> top-32 sorted desc ----------
__device__ __forceinline__ float sort_top32_64(float v0, float v1, unsigned lane) {
    #pragma unroll
    for (int k = 2; k <= 32; k <<= 1) {
        #pragma unroll
        for (int j = k >> 1; j >= 1; j >>= 1) {
            bool wmax = (((lane & k) == 0) == ((lane & j) == 0));
            float o0 = __shfl_xor_sync(0xffffffffu, v0, j);
            float o1 = __shfl_xor_sync(0xffffffffu, v1, j);
            v0 = wmax ? fmaxf(v0, o0) : fminf(v0, o0);
            v1 = wmax ? fmaxf(v1, o1) : fminf(v1, o1);
        }
    }
    // top-32 of two descending 32-lists: max(a[i], b[31-i]) is bitonic; clean-merge.
    float b1 = __shfl_sync(0xffffffffu, v1, 31 ^ lane);
    float s = fmaxf(v0, b1);
    #pragma unroll
    for (int j = 16; j >= 1; j >>= 1) {
        float o = __shfl_xor_sync(0xffffffffu, s, j);
        s = ((lane & j) == 0) ? fmaxf(s, o) : fminf(s, o);
    }
    return s;
}

// ---------- per-lane candidate mask from smem row (bit k = elem k >= T) ----------
__device__ __forceinline__ unsigned mask_from_smem(const float4* buf4, unsigned lane,
                                                   float T) {
    unsigned m = 0u;
    #pragma unroll
    for (int i = 0; i < 8; i++) {
        float4 v = buf4[i * 32 + lane];
        unsigned nib = 0u;
        if (v.x >= T) nib |= 1u;
        if (v.y >= T) nib |= 2u;
        if (v.z >= T) nib |= 4u;
        if (v.w >= T) nib |= 8u;
        m |= nib << (4 * i);
    }
    return m;
}

// ---------- exact fallback: binary-search the 30th-largest (cold, ~1% of rows) ----
__device__ __forceinline__ float find_thresh_smem(const float4* buf4, unsigned lane) {
    unsigned lo = 0u, hi = 0xFFFFFFFFu;   // invariant: count(key >= lo) >= KTOP
    while (lo < hi) {
        unsigned mid = lo + 1u + ((hi - lo - 1u) >> 1);
        int c = 0;
        #pragma unroll
        for (int i = 0; i < 8; i++) {
            float4 v = buf4[i * 32 + lane];
            c += (fmono(v.x) >= mid) + (fmono(v.y) >= mid) +
                 (fmono(v.z) >= mid) + (fmono(v.w) >= mid);
        }
        #pragma unroll
        for (int j = 16; j >= 1; j >>= 1) c += __shfl_xor_sync(0xffffffffu, c, j);
        if (c >= KTOP) lo = mid; else hi = mid - 1u;
    }
    return fdemono(lo);   // exact 30th-largest value of this row
}

// ---------- warp exclusive scan over per-lane counts ----------
__device__ __forceinline__ int warp_exscan(int c, unsigned lane, int &total) {
    int incl = c;
    #pragma unroll
    for (int d = 1; d < 32; d <<= 1) {
        int n = __shfl_up_sync(0xffffffffu, incl, d);
        if ((int)lane >= d) incl += n;
    }
    total = __shfl_sync(0xffffffffu, incl, 31);
    return incl - c;
}

__device__ __forceinline__ unsigned long long pack_vp(float v, unsigned pos) {
    return ((unsigned long long)__float_as_uint(v) << 32) | pos;
}

// ---------- nibble extraction: fixed indices, fully predicated, no vote loop ------
// slot ORDER is irrelevant (sort is symmetric): each lane writes its own
// candidates at [base, base+cnt). Wrap keeps memory safe in impossible overflows.
__device__ __forceinline__ void extract_nib(const float4* buf4, unsigned m, int base,
                                            unsigned lane, unsigned long long* slot) {
    int idx = base;
    const unsigned lane4 = lane * 4u;
    #pragma unroll
    for (int i = 0; i < 8; i++) {
        unsigned nib = (m >> (4 * i)) & 0xFu;
        if (nib) {
            float4 v = buf4[i * 32 + lane];
            unsigned pb = (unsigned)(128 * i) + lane4;
            if (nib & 1u) { slot[idx & (CAP - 1)] = pack_vp(v.x, pb + 0u); idx++; }
            if (nib & 2u) { slot[idx & (CAP - 1)] = pack_vp(v.y, pb + 1u); idx++; }
            if (nib & 4u) { slot[idx & (CAP - 1)] = pack_vp(v.z, pb + 2u); idx++; }
            if (nib & 8u) { slot[idx & (CAP - 1)] = pack_vp(v.w, pb + 3u); idx++; }
        }
    }
}

// ---------- candidate selection for one row resident in shared ----------
__device__ __forceinline__ void select_candidates(const float4* buf4, unsigned lane,
                                                  unsigned long long* slot) {
    const unsigned long long NEG = ((unsigned long long)0xFF800000u) << 32;  // -inf
    slot[lane]      = NEG;
    slot[lane + 32] = NEG;
    float T = 1.695f;                       // ~46 expected candidates for N(0,1)
    unsigned m = mask_from_smem(buf4, lane, T);
    int total, base = warp_exscan(__popc(m), lane, total);
    if (total < KTOP || total > CAP) {      // warp-uniform cold path (~1%)
        T = find_thresh_smem(buf4, lane);   // exact 30th-largest
        m = mask_from_smem(buf4, lane, T);
        base = warp_exscan(__popc(m), lane, total);
    }
    __syncwarp();                           // pads visible before candidate writes
    extract_nib(buf4, m, base, lane, slot);
    __syncwarp();                           // slots complete
}

extern "C" __global__ void __launch_bounds__(TPB, 3)
topk_fused(const float* __restrict__ pred, const float* __restrict__ target,
           float* __restrict__ out, int nrows, int nblk) {
    extern __shared__ unsigned char dsm[];
    __shared__ int   s_rc[WPB];
    __shared__ float s_rd[WPB];

    const unsigned lane = threadIdx.x & 31u;
    const unsigned warp = threadIdx.x >> 5;
    const int nwarps = nblk * WPB;
    const int gw = blockIdx.x * WPB + (int)warp;

    const float4* bA4 = (const float4*)((float*)(dsm + OFF_BUFA) + warp * COLS);
    const float4* bB4 = (const float4*)((float*)(dsm + OFF_BUFB) + warp * COLS);
    unsigned long long* slot = (unsigned long long*)(dsm + OFF_SLOT) + warp * CAP;
    unsigned* bm = (unsigned*)(dsm + OFF_BM) + warp * 32;
    const unsigned sbA = smem_u32(bA4);
    const unsigned sbB = smem_u32(bB4);

    int   csum = 0;      // per-lane partial, reduced once after the loop
    float dsum = 0.0f;   // per-lane partial (lane k: k-th order-statistic diffs)

    bm[lane] = 0u;       // ordered before first marking by selects' syncwarps

    // prologue: prefetch first row pair (two groups: pred, target)
    const float4* prow = (const float4*)pred   + (size_t)gw * (COLS / 4);
    const float4* trow = (const float4*)target + (size_t)gw * (COLS / 4);
    const size_t stride4 = (size_t)nwarps * (COLS / 4);
    #pragma unroll
    for (int i = 0; i < 8; i++)
        cp_async16(sbA + (unsigned)(i * 32 + lane) * 16u, prow + i * 32 + lane);
    cp_commit();
    #pragma unroll
    for (int i = 0; i < 8; i++)
        cp_async16(sbB + (unsigned)(i * 32 + lane) * 16u, trow + i * 32 + lane);
    cp_commit();

    for (int row = gw; row < nrows; row += nwarps) {
        const bool has_next = (row + nwarps) < nrows;

        // ---- pred row (buffer A) ----
        cp_wait1();                          // pred_i landed (target_i may be pending)
        __syncwarp();
        select_candidates(bA4, lane, slot);

        prow += stride4;                     // A dead: prefetch next pred
        if (has_next) {
            #pragma unroll
            for (int i = 0; i < 8; i++)
                cp_async16(sbA + (unsigned)(i * 32 + lane) * 16u, prow + i * 32 + lane);
        }
        cp_commit();

        float ps, thrp;
        {
            unsigned long long q0 = slot[lane], q1 = slot[lane + 32];
            float cv0 = __uint_as_float((unsigned)(q0 >> 32));
            float cv1 = __uint_as_float((unsigned)(q1 >> 32));
            int   p0  = (int)(q0 & 1023u), p1 = (int)(q1 & 1023u);
            ps = sort_top32_64(cv0, cv1, lane);
            thrp = __shfl_sync(0xffffffffu, ps, KTOP - 1);
            if (cv0 >= thrp) atomicOr(&bm[p0 >> 5], 1u << (p0 & 31));
            if (cv1 >= thrp) atomicOr(&bm[p1 >> 5], 1u << (p1 & 31));
        }

        // ---- target row (buffer B) ----
        cp_wait1();                          // target_i landed (next pred pending)
        __syncwarp();                        // also orders bm marking before probe
        select_candidates(bB4, lane, slot);

        trow += stride4;                     // B dead: prefetch next target
        if (has_next) {
            #pragma unroll
            for (int i = 0; i < 8; i++)
                cp_async16(sbB + (unsigned)(i * 32 + lane) * 16u, trow + i * 32 + lane);
        }
        cp_commit();
        {
            unsigned long long q0 = slot[lane], q1 = slot[lane + 32];
            float cv0 = __uint_as_float((unsigned)(q0 >> 32));
            float cv1 = __uint_as_float((unsigned)(q1 >> 32));
            int   p0  = (int)(q0 & 1023u), p1 = (int)(q1 & 1023u);
            float ts = sort_top32_64(cv0, cv1, lane);
            float thrt = __shfl_sync(0xffffffffu, ts, KTOP - 1);

            if (cv0 >= thrt) csum += (int)((bm[p0 >> 5] >> (p0 & 31)) & 1u);
            if (cv1 >= thrt) csum += (int)((bm[p1 >> 5] >> (p1 & 31)) & 1u);
            __syncwarp();                    // probes done before reset
            bm[lane] = 0u;                   // ready for next iteration

            dsum += (lane < KTOP) ? fabsf(ps - ts) : 0.0f;
        }
    }

    // single warp reduction at the end
    #pragma unroll
    for (int j = 16; j >= 1; j >>= 1) {
        csum += __shfl_xor_sync(0xffffffffu, csum, j);
        dsum += __shfl_xor_sync(0xffffffffu, dsum, j);
    }

    if (lane == 0) { s_rc[warp] = csum; s_rd[warp] = dsum; }
    __syncthreads();

    if (threadIdx.x == 0) {
        int   ci = 0;
        float df = 0.0f;
        #pragma unroll
        for (int w = 0; w < WPB; w++) { ci += s_rc[w]; df += s_rd[w]; }
        atomicAdd(&g_cnt, (unsigned long long)ci);
        atomicAdd(&g_diffx,
                  (unsigned long long)__double2ll_rn((double)df * 1073741824.0));
        __threadfence();
        unsigned t = atomicAdd(&g_arrive, 1u);
        if (t == (unsigned)(nblk - 1)) {               // last block finalizes
            unsigned long long C = atomicAdd(&g_cnt, 0ULL);
            unsigned long long D = atomicAdd(&g_diffx, 0ULL);
            out[0] = (float)((double)C / (30.0 * (double)nrows));          // acc
            out[1] = (float)((double)D / (1073741824.0 * 30.0));           // diff
            g_cnt = 0ULL; g_diffx = 0ULL; g_arrive = 0u;   // reset for next replay
            __threadfence();
        }
    }
}

extern "C" void kernel_launch(void* const* d_in, const int* in_sizes, int n_in,
                              void* d_out, int out_size) {
    const float* pred   = (const float*)d_in[0];
    const float* target = (const float*)d_in[1];
    int nrows = in_sizes[0] / COLS;

    int sms = 148;
    cudaDeviceGetAttribute(&sms, cudaDevAttrMultiProcessorCount, 0);  // host query
    int nblk = 3 * sms;                    // exactly one resident wave (3 blocks/SM)

    cudaFuncSetAttribute(topk_fused, cudaFuncAttributeMaxDynamicSharedMemorySize,
                         SMEM_SZ);
    topk_fused<<<nblk, TPB, SMEM_SZ>>>(pred, target, (float*)d_out, nrows, nblk);
}

// round 15
// speedup vs baseline: 1.1084x; 1.1084x over previous
#include <cuda_runtime.h>
#include <cstdint>
#include <math_constants.h>

#define KTOP    30
#define COLS    1024
#define WPB     13           // warps per block (2 blocks/SM -> 26 warps/SM)
#define TPB     (WPB * 32)
#define CAP     64           // candidate slots per warp (2 regs/lane in sort)

// dynamic smem layout (bytes)
#define OFF_BUFA  0
#define OFF_BUFB  (WPB * COLS * 4)
#define OFF_SLOT  (2 * WPB * COLS * 4)
#define OFF_BM    (OFF_SLOT + WPB * CAP * 8)
#define SMEM_SZ   (OFF_BM + WPB * 32 * 4)

// deterministic global accumulators (integer atomics commute exactly)
__device__ unsigned long long g_cnt;     // sum of per-row intersection counts
__device__ unsigned long long g_diffx;   // sum of per-block diff, fixed-point 2^30
__device__ unsigned g_arrive;

// ---------- cp.async helpers ----------
__device__ __forceinline__ unsigned smem_u32(const void* p) {
    return (unsigned)__cvta_generic_to_shared(p);
}
__device__ __forceinline__ void cp_async16(unsigned saddr, const void* gptr) {
    asm volatile("cp.async.cg.shared.global [%0], [%1], 16;\n"
                 :: "r"(saddr), "l"(gptr) : "memory");
}
__device__ __forceinline__ void cp_commit() {
    asm volatile("cp.async.commit_group;\n" ::: "memory");
}
__device__ __forceinline__ void cp_wait1() {   // wait until <=1 group pending
    asm volatile("cp.async.wait_group 1;\n" ::: "memory");
}

// ---------- monotone float<->uint key (only used in the cold fallback) ----------
__device__ __forceinline__ unsigned fmono(float f) {
    unsigned u = __float_as_uint(f);
    return u ^ (0x80000000u | (unsigned)((int)u >> 31));
}
__device__ __forceinline__ float fdemono(unsigned k) {
    unsigned u = k ^ (0x80000000u | ~(unsigned)((int)k >> 31));
    return __uint_as_float(u);
}

// ---------- cross-lane bitonic: 2 regs/lane (64 values) -> top-32 sorted desc ----------
__device__ __forceinline__ float sort_top32_64(float v0, float v1, unsigned lane) {
    #pragma unroll
    for (int k = 2; k <= 32; k <<= 1) {
        #pragma unroll
        for (int j = k >> 1; j >= 1; j >>= 1) {
            bool wmax = (((lane & k) == 0) == ((lane & j) == 0));
            float o0 = __shfl_xor_sync(0xffffffffu, v0, j);
            float o1 = __shfl_xor_sync(0xffffffffu, v1, j);
            v0 = wmax ? fmaxf(v0, o0) : fminf(v0, o0);
            v1 = wmax ? fmaxf(v1, o1) : fminf(v1, o1);
        }
    }
    // top-32 of two descending 32-lists: max(a[i], b[31-i]) is bitonic; clean-merge.
    float b1 = __shfl_sync(0xffffffffu, v1, 31 ^ lane);
    float s = fmaxf(v0, b1);
    #pragma unroll
    for (int j = 16; j >= 1; j >>= 1) {
        float o = __shfl_xor_sync(0xffffffffu, s, j);
        s = ((lane & j) == 0) ? fmaxf(s, o) : fminf(s, o);
    }
    return s;
}

// ---------- exact fallback: binary-search the 30th-largest value (cold path) ----------
__device__ __forceinline__ float find_thresh(const float4 (&v)[8], unsigned lane) {
    unsigned lo = 0u, hi = 0xFFFFFFFFu;   // invariant: count(key >= lo) >= KTOP
    while (lo < hi) {
        unsigned mid = lo + 1u + ((hi - lo - 1u) >> 1);
        int c = 0;
        #pragma unroll
        for (int i = 0; i < 8; i++) {
            c += (fmono(v[i].x) >= mid) + (fmono(v[i].y) >= mid) +
                 (fmono(v[i].z) >= mid) + (fmono(v[i].w) >= mid);
        }
        #pragma unroll
        for (int j = 16; j >= 1; j >>= 1) c += __shfl_xor_sync(0xffffffffu, c, j);
        if (c >= KTOP) lo = mid; else hi = mid - 1u;
    }
    return fdemono(lo);   // exact 30th-largest value of this row
}

// ---------- per-lane candidate mask (bit k = element k of this lane >= T) ----------
__device__ __forceinline__ unsigned build_mask(const float4 (&v)[8], float T) {
    unsigned m = 0u;
    #pragma unroll
    for (int i = 0; i < 8; i++) {
        if (v[i].x >= T) m |= 1u << (4 * i + 0);
        if (v[i].y >= T) m |= 1u << (4 * i + 1);
        if (v[i].z >= T) m |= 1u << (4 * i + 2);
        if (v[i].w >= T) m |= 1u << (4 * i + 3);
    }
    return m;
}

// ---------- warp exclusive scan over per-lane counts ----------
__device__ __forceinline__ int warp_exscan(int c, unsigned lane, int &total) {
    int incl = c;
    #pragma unroll
    for (int d = 1; d < 32; d <<= 1) {
        int n = __shfl_up_sync(0xffffffffu, incl, d);
        if ((int)lane >= d) incl += n;
    }
    total = __shfl_sync(0xffffffffu, incl, 31);
    return incl - c;
}

// ---------- ffs extraction: candidates -> packed (valbits,pos) u64 slots ----------
__device__ __forceinline__ void extract(unsigned m, int base, unsigned lane,
                                        const float* buf, unsigned long long* slot) {
    int idx = base;
    const unsigned lane4 = lane * 4u;
    while (__any_sync(0xffffffffu, m != 0u)) {
        if (m) {
            int k = __ffs(m) - 1;
            m &= m - 1u;
            int pos = ((k >> 2) << 7) | (int)(lane4 + (k & 3));   // 128*(k/4)+4*lane+(k&3)
            float val = buf[pos];
            unsigned long long pk =
                ((unsigned long long)__float_as_uint(val) << 32) | (unsigned)pos;
            slot[idx & (CAP - 1)] = pk;     // wrap = mem safety; bad rows hit fallback
            idx++;
        }
    }
}

// ---------- candidate selection for one row resident in shared ----------
__device__ __forceinline__ void select_candidates(const float4 (&v)[8], unsigned lane,
                                                  const float* buf,
                                                  unsigned long long* slot) {
    const unsigned long long NEG = ((unsigned long long)0xFF800000u) << 32;  // -inf
    slot[lane]      = NEG;
    slot[lane + 32] = NEG;
    float T = 1.695f;                       // ~46 expected candidates for N(0,1)
    unsigned m = build_mask(v, T);
    int total, base = warp_exscan(__popc(m), lane, total);
    if (total < KTOP || total > CAP) {      // warp-uniform cold path (~1%)
        T = find_thresh(v, lane);           // exact 30th-largest
        m = build_mask(v, T);
        base = warp_exscan(__popc(m), lane, total);
    }
    __syncwarp();                           // pads visible before extraction writes
    extract(m, base, lane, buf, slot);
    __syncwarp();                           // slots complete
}

extern "C" __global__ void __launch_bounds__(TPB, 2)
topk_fused(const float* __restrict__ pred, const float* __restrict__ target,
           float* __restrict__ out, int nrows, int nblk) {
    extern __shared__ unsigned char dsm[];
    __shared__ int   s_rc[WPB];
    __shared__ float s_rd[WPB];

    const unsigned lane = threadIdx.x & 31u;
    const unsigned warp = threadIdx.x >> 5;
    const int nwarps = nblk * WPB;
    const int gw = blockIdx.x * WPB + (int)warp;

    float* bA = (float*)(dsm + OFF_BUFA) + warp * COLS;
    float* bB = (float*)(dsm + OFF_BUFB) + warp * COLS;
    unsigned long long* slot = (unsigned long long*)(dsm + OFF_SLOT) + warp * CAP;
    unsigned* bm = (unsigned*)(dsm + OFF_BM) + warp * 32;
    const unsigned sbA = smem_u32(bA);
    const unsigned sbB = smem_u32(bB);

    int   csum = 0;
    float dsum = 0.0f;

    // prologue: prefetch first row pair (two groups: pred, target)
    const float4* prow = (const float4*)pred   + (size_t)gw * (COLS / 4);
    const float4* trow = (const float4*)target + (size_t)gw * (COLS / 4);
    const size_t stride4 = (size_t)nwarps * (COLS / 4);
    #pragma unroll
    for (int i = 0; i < 8; i++)
        cp_async16(sbA + (unsigned)(i * 32 + lane) * 16u, prow + i * 32 + lane);
    cp_commit();
    #pragma unroll
    for (int i = 0; i < 8; i++)
        cp_async16(sbB + (unsigned)(i * 32 + lane) * 16u, trow + i * 32 + lane);
    cp_commit();

    for (int row = gw; row < nrows; row += nwarps) {
        const bool has_next = (row + nwarps) < nrows;
        bm[lane] = 0u;                      // ordered by syncwarps in select_candidates

        // ---- pred row (buffer A) ----
        cp_wait1();                          // pred_i landed (target_i may be pending)
        __syncwarp();
        float ps, thrp;
        {
            float4 pv[8];
            #pragma unroll
            for (int i = 0; i < 8; i++) pv[i] = ((const float4*)bA)[i * 32 + lane];
            select_candidates(pv, lane, bA, slot);
        }
        prow += stride4;                     // A dead: prefetch next pred
        if (has_next) {
            #pragma unroll
            for (int i = 0; i < 8; i++)
                cp_async16(sbA + (unsigned)(i * 32 + lane) * 16u, prow + i * 32 + lane);
        }
        cp_commit();
        {
            unsigned long long q0 = slot[lane], q1 = slot[lane + 32];
            float cv0 = __uint_as_float((unsigned)(q0 >> 32));
            float cv1 = __uint_as_float((unsigned)(q1 >> 32));
            int   p0  = (int)(q0 & 1023u), p1 = (int)(q1 & 1023u);
            ps = sort_top32_64(cv0, cv1, lane);
            thrp = __shfl_sync(0xffffffffu, ps, KTOP - 1);
            if (cv0 >= thrp) atomicOr(&bm[p0 >> 5], 1u << (p0 & 31));
            if (cv1 >= thrp) atomicOr(&bm[p1 >> 5], 1u << (p1 & 31));
        }

        // ---- target row (buffer B) ----
        cp_wait1();                          // target_i landed (next pred pending)
        __syncwarp();                        // also orders bm marking before probe
        {
            float4 tv[8];
            #pragma unroll
            for (int i = 0; i < 8; i++) tv[i] = ((const float4*)bB)[i * 32 + lane];
            select_candidates(tv, lane, bB, slot);
        }
        trow += stride4;                     // B dead: prefetch next target
        if (has_next) {
            #pragma unroll
            for (int i = 0; i < 8; i++)
                cp_async16(sbB + (unsigned)(i * 32 + lane) * 16u, trow + i * 32 + lane);
        }
        cp_commit();
        {
            unsigned long long q0 = slot[lane], q1 = slot[lane + 32];
            float cv0 = __uint_as_float((unsigned)(q0 >> 32));
            float cv1 = __uint_as_float((unsigned)(q1 >> 32));
            int   p0  = (int)(q0 & 1023u), p1 = (int)(q1 & 1023u);
            float ts = sort_top32_64(cv0, cv1, lane);
            float thrt = __shfl_sync(0xffffffffu, ts, KTOP - 1);

            int cnt = 0;
            if (cv0 >= thrt) cnt += (int)((bm[p0 >> 5] >> (p0 & 31)) & 1u);
            if (cv1 >= thrt) cnt += (int)((bm[p1 >> 5] >> (p1 & 31)) & 1u);
            csum += __reduce_add_sync(0xffffffffu, cnt);   // also orders probe/reset

            float d = (lane < KTOP) ? fabsf(ps - ts) : 0.0f;
            #pragma unroll
            for (int j = 16; j >= 1; j >>= 1) d += __shfl_xor_sync(0xffffffffu, d, j);
            dsum += d;
        }
    }

    if (lane == 0) { s_rc[warp] = csum; s_rd[warp] = dsum; }
    __syncthreads();

    if (threadIdx.x == 0) {
        int   ci = 0;
        float df = 0.0f;
        #pragma unroll
        for (int w = 0; w < WPB; w++) { ci += s_rc[w]; df += s_rd[w]; }
        atomicAdd(&g_cnt, (unsigned long long)ci);
        atomicAdd(&g_diffx,
                  (unsigned long long)__double2ll_rn((double)df * 1073741824.0));
        __threadfence();
        unsigned t = atomicAdd(&g_arrive, 1u);
        if (t == (unsigned)(nblk - 1)) {               // last block finalizes
            unsigned long long C = atomicAdd(&g_cnt, 0ULL);
            unsigned long long D = atomicAdd(&g_diffx, 0ULL);
            out[0] = (float)((double)C / (30.0 * (double)nrows));          // acc
            out[1] = (float)((double)D / (1073741824.0 * 30.0));           // diff
            g_cnt = 0ULL; g_diffx = 0ULL; g_arrive = 0u;   // reset for next replay
            __threadfence();
        }
    }
}

extern "C" void kernel_launch(void* const* d_in, const int* in_sizes, int n_in,
                              void* d_out, int out_size) {
    const float* pred   = (const float*)d_in[0];
    const float* target = (const float*)d_in[1];
    int nrows = in_sizes[0] / COLS;

    int sms = 148;
    cudaDeviceGetAttribute(&sms, cudaDevAttrMultiProcessorCount, 0);  // host query
    int nblk = 2 * sms;                    // exactly one resident wave (2 blocks/SM)

    cudaFuncSetAttribute(topk_fused, cudaFuncAttributeMaxDynamicSharedMemorySize,
                         SMEM_SZ);
    topk_fused<<<nblk, TPB, SMEM_SZ>>>(pred, target, (float*)d_out, nrows, nblk);
}

// round 17
// speedup vs baseline: 1.2151x; 1.0963x over previous
#include <cuda_runtime.h>
#include <cstdint>
#include <math_constants.h>

#define KTOP    30
#define COLS    1024
#define WPB     8            // warps per block
#define TPB     (WPB * 32)
#define CAP     64           // candidate slots per warp (2 regs/lane in sort)

// dynamic smem layout (bytes)
#define OFF_BUFA  0
#define OFF_BUFB  (WPB * COLS * 4)
#define OFF_SLOT  (2 * WPB * COLS * 4)
#define OFF_BM    (OFF_SLOT + WPB * CAP * 8)
#define SMEM_SZ   (OFF_BM + WPB * 32 * 4)

// deterministic global accumulators (integer atomics commute exactly)
__device__ unsigned long long g_cnt;     // sum of per-row intersection counts
__device__ unsigned long long g_diffx;   // sum of per-block diff, fixed-point 2^30
__device__ unsigned g_arrive;

// ---------- cp.async helpers ----------
__device__ __forceinline__ unsigned smem_u32(const void* p) {
    return (unsigned)__cvta_generic_to_shared(p);
}
__device__ __forceinline__ void cp_async16(unsigned saddr, const void* gptr) {
    asm volatile("cp.async.cg.shared.global [%0], [%1], 16;\n"
                 :: "r"(saddr), "l"(gptr) : "memory");
}
__device__ __forceinline__ void cp_commit() {
    asm volatile("cp.async.commit_group;\n" ::: "memory");
}
__device__ __forceinline__ void cp_wait1() {   // wait until <=1 group pending
    asm volatile("cp.async.wait_group 1;\n" ::: "memory");
}

// ---------- monotone float<->uint key (only used in the cold fallback) ----------
__device__ __forceinline__ unsigned fmono(float f) {
    unsigned u = __float_as_uint(f);
    return u ^ (0x80000000u | (unsigned)((int)u >> 31));
}
__device__ __forceinline__ float fdemono(unsigned k) {
    unsigned u = k ^ (0x80000000u | ~(unsigned)((int)k >> 31));
    return __uint_as_float(u);
}

// ---------- cross-lane bitonic: 2 regs/lane (64 values) -> top-32 sorted desc ----------
__device__ __forceinline__ float sort_top32_64(float v0, float v1, unsigned lane) {
    #pragma unroll
    for (int k = 2; k <= 32; k <<= 1) {
        #pragma unroll
        for (int j = k >> 1; j >= 1; j >>= 1) {
            bool wmax = (((lane & k) == 0) == ((lane & j) == 0));
            float o0 = __shfl_xor_sync(0xffffffffu, v0, j);
            float o1 = __shfl_xor_sync(0xffffffffu, v1, j);
            v0 = wmax ? fmaxf(v0, o0) : fminf(v0, o0);
            v1 = wmax ? fmaxf(v1, o1) : fminf(v1, o1);
        }
    }
    // top-32 of two descending 32-lists: max(a[i], b[31-i]) is bitonic; clean-merge.
    float b1 = __shfl_sync(0xffffffffu, v1, 31 ^ lane);
    float s = fmaxf(v0, b1);
    #pragma unroll
    for (int j = 16; j >= 1; j >>= 1) {
        float o = __shfl_xor_sync(0xffffffffu, s, j);
        s = ((lane & j) == 0) ? fmaxf(s, o) : fminf(s, o);
    }
    return s;
}

// ---------- exact fallback: binary-search the 30th-largest value (cold path) ----------
__device__ __forceinline__ float find_thresh(const float4 (&v)[8], unsigned lane) {
    unsigned lo = 0u, hi = 0xFFFFFFFFu;   // invariant: count(key >= lo) >= KTOP
    while (lo < hi) {
        unsigned mid = lo + 1u + ((hi - lo - 1u) >> 1);
        int c = 0;
        #pragma unroll
        for (int i = 0; i < 8; i++) {
            c += (fmono(v[i].x) >= mid) + (fmono(v[i].y) >= mid) +
                 (fmono(v[i].z) >= mid) + (fmono(v[i].w) >= mid);
        }
        #pragma unroll
        for (int j = 16; j >= 1; j >>= 1) c += __shfl_xor_sync(0xffffffffu, c, j);
        if (c >= KTOP) lo = mid; else hi = mid - 1u;
    }
    return fdemono(lo);   // exact 30th-largest value of this row
}

// ---------- per-lane candidate mask (bit k = element k of this lane >= T) ----------
__device__ __forceinline__ unsigned build_mask(const float4 (&v)[8], float T) {
    unsigned m = 0u;
    #pragma unroll
    for (int i = 0; i < 8; i++) {
        if (v[i].x >= T) m |= 1u << (4 * i + 0);
        if (v[i].y >= T) m |= 1u << (4 * i + 1);
        if (v[i].z >= T) m |= 1u << (4 * i + 2);
        if (v[i].w >= T) m |= 1u << (4 * i + 3);
    }
    return m;
}

// ---------- warp exclusive scan over per-lane counts ----------
__device__ __forceinline__ int warp_exscan(int c, unsigned lane, int &total) {
    int incl = c;
    #pragma unroll
    for (int d = 1; d < 32; d <<= 1) {
        int n = __shfl_up_sync(0xffffffffu, incl, d);
        if ((int)lane >= d) incl += n;
    }
    total = __shfl_sync(0xffffffffu, incl, 31);
    return incl - c;
}

// ---------- ffs extraction: candidates -> packed (valbits,pos) u64 slots ----------
__device__ __forceinline__ void extract(unsigned m, int base, unsigned lane,
                                        const float* buf, unsigned long long* slot) {
    int idx = base;
    const unsigned lane4 = lane * 4u;
    while (__any_sync(0xffffffffu, m != 0u)) {
        if (m) {
            int k = __ffs(m) - 1;
            m &= m - 1u;
            int pos = ((k >> 2) << 7) | (int)(lane4 + (k & 3));   // 128*(k/4)+4*lane+(k&3)
            float val = buf[pos];
            unsigned long long pk =
                ((unsigned long long)__float_as_uint(val) << 32) | (unsigned)pos;
            slot[idx & (CAP - 1)] = pk;     // wrap = mem safety; bad rows hit fallback
            idx++;
        }
    }
}

// ---------- candidate selection for one row resident in shared ----------
__device__ __forceinline__ void select_candidates(const float4 (&v)[8], unsigned lane,
                                                  const float* buf,
                                                  unsigned long long* slot) {
    const unsigned long long NEG = ((unsigned long long)0xFF800000u) << 32;  // -inf
    slot[lane]      = NEG;
    slot[lane + 32] = NEG;
    float T = 1.695f;                       // ~46 expected candidates for N(0,1)
    unsigned m = build_mask(v, T);
    int total, base = warp_exscan(__popc(m), lane, total);
    if (total < KTOP || total > CAP) {      // warp-uniform cold path (~1%)
        T = find_thresh(v, lane);           // exact 30th-largest
        m = build_mask(v, T);
        base = warp_exscan(__popc(m), lane, total);
    }
    __syncwarp();                           // pads visible before extraction writes
    extract(m, base, lane, buf, slot);
    __syncwarp();                           // slots complete
}

extern "C" __global__ void __launch_bounds__(TPB, 3)
topk_fused(const float* __restrict__ pred, const float* __restrict__ target,
           float* __restrict__ out, int nrows, int nblk) {
    extern __shared__ unsigned char dsm[];
    __shared__ int   s_rc[WPB];
    __shared__ float s_rd[WPB];

    const unsigned lane = threadIdx.x & 31u;
    const unsigned warp = threadIdx.x >> 5;
    const int nwarps = nblk * WPB;
    const int gw = blockIdx.x * WPB + (int)warp;

    float* bA = (float*)(dsm + OFF_BUFA) + warp * COLS;
    float* bB = (float*)(dsm + OFF_BUFB) + warp * COLS;
    unsigned long long* slot = (unsigned long long*)(dsm + OFF_SLOT) + warp * CAP;
    unsigned* bm = (unsigned*)(dsm + OFF_BM) + warp * 32;
    const unsigned sbA = smem_u32(bA);
    const unsigned sbB = smem_u32(bB);

    int   csum = 0;
    float dsum = 0.0f;

    // prologue: prefetch first row pair (two groups: pred, target)
    const float4* prow = (const float4*)pred   + (size_t)gw * (COLS / 4);
    const float4* trow = (const float4*)target + (size_t)gw * (COLS / 4);
    const size_t stride4 = (size_t)nwarps * (COLS / 4);
    #pragma unroll
    for (int i = 0; i < 8; i++)
        cp_async16(sbA + (unsigned)(i * 32 + lane) * 16u, prow + i * 32 + lane);
    cp_commit();
    #pragma unroll
    for (int i = 0; i < 8; i++)
        cp_async16(sbB + (unsigned)(i * 32 + lane) * 16u, trow + i * 32 + lane);
    cp_commit();

    for (int row = gw; row < nrows; row += nwarps) {
        const bool has_next = (row + nwarps) < nrows;
        bm[lane] = 0u;                      // ordered by syncwarps in select_candidates

        // ---- pred row (buffer A) ----
        cp_wait1();                          // pred_i landed (target_i may be pending)
        __syncwarp();
        float ps, thrp;
        {
            float4 pv[8];
            #pragma unroll
            for (int i = 0; i < 8; i++) pv[i] = ((const float4*)bA)[i * 32 + lane];
            select_candidates(pv, lane, bA, slot);
        }
        prow += stride4;                     // A dead: prefetch next pred
        if (has_next) {
            #pragma unroll
            for (int i = 0; i < 8; i++)
                cp_async16(sbA + (unsigned)(i * 32 + lane) * 16u, prow + i * 32 + lane);
        }
        cp_commit();
        {
            unsigned long long q0 = slot[lane], q1 = slot[lane + 32];
            float cv0 = __uint_as_float((unsigned)(q0 >> 32));
            float cv1 = __uint_as_float((unsigned)(q1 >> 32));
            int   p0  = (int)(q0 & 1023u), p1 = (int)(q1 & 1023u);
            ps = sort_top32_64(cv0, cv1, lane);
            thrp = __shfl_sync(0xffffffffu, ps, KTOP - 1);
            if (cv0 >= thrp) atomicOr(&bm[p0 >> 5], 1u << (p0 & 31));
            if (cv1 >= thrp) atomicOr(&bm[p1 >> 5], 1u << (p1 & 31));
        }

        // ---- target row (buffer B) ----
        cp_wait1();                          // target_i landed (next pred pending)
        __syncwarp();                        // also orders bm marking before probe
        {
            float4 tv[8];
            #pragma unroll
            for (int i = 0; i < 8; i++) tv[i] = ((const float4*)bB)[i * 32 + lane];
            select_candidates(tv, lane, bB, slot);
        }
        trow += stride4;                     // B dead: prefetch next target
        if (has_next) {
            #pragma unroll
            for (int i = 0; i < 8; i++)
                cp_async16(sbB + (unsigned)(i * 32 + lane) * 16u, trow + i * 32 + lane);
        }
        cp_commit();
        {
            unsigned long long q0 = slot[lane], q1 = slot[lane + 32];
            float cv0 = __uint_as_float((unsigned)(q0 >> 32));
            float cv1 = __uint_as_float((unsigned)(q1 >> 32));
            int   p0  = (int)(q0 & 1023u), p1 = (int)(q1 & 1023u);
            float ts = sort_top32_64(cv0, cv1, lane);
            float thrt = __shfl_sync(0xffffffffu, ts, KTOP - 1);

            int cnt = 0;
            if (cv0 >= thrt) cnt += (int)((bm[p0 >> 5] >> (p0 & 31)) & 1u);
            if (cv1 >= thrt) cnt += (int)((bm[p1 >> 5] >> (p1 & 31)) & 1u);
            csum += __reduce_add_sync(0xffffffffu, cnt);

            float d = (lane < KTOP) ? fabsf(ps - ts) : 0.0f;
            #pragma unroll
            for (int j = 16; j >= 1; j >>= 1) d += __shfl_xor_sync(0xffffffffu, d, j);
            dsum += d;
        }
    }

    if (lane == 0) { s_rc[warp] = csum; s_rd[warp] = dsum; }
    __syncthreads();

    if (threadIdx.x == 0) {
        int   ci = 0;
        float df = 0.0f;
        #pragma unroll
        for (int w = 0; w < WPB; w++) { ci += s_rc[w]; df += s_rd[w]; }
        atomicAdd(&g_cnt, (unsigned long long)ci);
        atomicAdd(&g_diffx,
                  (unsigned long long)__double2ll_rn((double)df * 1073741824.0));
        __threadfence();
        unsigned t = atomicAdd(&g_arrive, 1u);
        if (t == (unsigned)(nblk - 1)) {               // last block finalizes
            unsigned long long C = atomicAdd(&g_cnt, 0ULL);
            unsigned long long D = atomicAdd(&g_diffx, 0ULL);
            out[0] = (float)((double)C / (30.0 * (double)nrows));          // acc
            out[1] = (float)((double)D / (1073741824.0 * 30.0));           // diff
            g_cnt = 0ULL; g_diffx = 0ULL; g_arrive = 0u;   // reset for next replay
            __threadfence();
        }
    }
}

extern "C" void kernel_launch(void* const* d_in, const int* in_sizes, int n_in,
                              void* d_out, int out_size) {
    const float* pred   = (const float*)d_in[0];
    const float* target = (const float*)d_in[1];
    int nrows = in_sizes[0] / COLS;

    int sms = 148;
    cudaDeviceGetAttribute(&sms, cudaDevAttrMultiProcessorCount, 0);  // host query
    int nblk = 3 * sms;          // exactly 3 resident blocks on EVERY SM (balanced wave)

    cudaFuncSetAttribute(topk_fused, cudaFuncAttributeMaxDynamicSharedMemorySize,
                         SMEM_SZ);
    topk_fused<<<nblk, TPB, SMEM_SZ>>>(pred, target, (float*)d_out, nrows, nblk);
}